// round 8
// baseline (speedup 1.0000x reference)
#include <cuda_runtime.h>
#include <cstdint>

#define N_NODES 8192
#define F_DIM   256
#define KSPLIT  4
#define KCHUNK  (N_NODES / KSPLIT)   // 2048

// Scratch (no cudaMalloc allowed)
__device__ float g_hT[(size_t)F_DIM * N_NODES];            // rna(neigh_W @ feat^T) [256][8192]
__device__ float g_agg[(size_t)N_NODES * F_DIM];           // (adj@h)/deg, tf32-rounded
__device__ float g_feat[(size_t)N_NODES * F_DIM];          // tf32-rounded features
__device__ float g_part[(size_t)KSPLIT * N_NODES * F_DIM]; // split-K partials (32MB)
__device__ float g_rowp[(size_t)KSPLIT * N_NODES];         // partial rowsums

// ---------------------------------------------------------------------------
// helpers
// ---------------------------------------------------------------------------
__device__ __forceinline__ void cp_async16(uint32_t s, const void* g) {
    asm volatile("cp.async.cg.shared.global [%0], [%1], 16;\n" :: "r"(s), "l"(g));
}
__device__ __forceinline__ void cp_commit() { asm volatile("cp.async.commit_group;\n"); }
template <int N> __device__ __forceinline__ void cp_wait() {
    asm volatile("cp.async.wait_group %0;\n" :: "n"(N));
}
__device__ __forceinline__ float rna_tf32(float f) {
    uint32_t r;
    asm("cvt.rna.tf32.f32 %0, %1;\n" : "=r"(r) : "f"(f));
    return __uint_as_float(r);
}
__device__ __forceinline__ void mma_tf32(float* c, const uint32_t* a, const uint32_t* b) {
    asm volatile(
        "mma.sync.aligned.m16n8k8.row.col.f32.tf32.tf32.f32 "
        "{%0,%1,%2,%3}, {%4,%5,%6,%7}, {%8,%9}, {%0,%1,%2,%3};\n"
        : "+f"(c[0]), "+f"(c[1]), "+f"(c[2]), "+f"(c[3])
        : "r"(a[0]), "r"(a[1]), "r"(a[2]), "r"(a[3]), "r"(b[0]), "r"(b[1]));
}
__device__ __forceinline__ void ldsm_x4(uint32_t& r0, uint32_t& r1, uint32_t& r2,
                                        uint32_t& r3, uint32_t a) {
    asm volatile("ldmatrix.sync.aligned.m8n8.x4.shared.b16 {%0,%1,%2,%3}, [%4];\n"
                 : "=r"(r0), "=r"(r1), "=r"(r2), "=r"(r3) : "r"(a));
}

// ---------------------------------------------------------------------------
__global__ void round_copy_kernel(const float* __restrict__ src, float* __restrict__ dst) {
    const size_t i = (size_t)(blockIdx.x * blockDim.x + threadIdx.x) * 4;
    float4 v = *reinterpret_cast<const float4*>(src + i);
    v.x = rna_tf32(v.x); v.y = rna_tf32(v.y);
    v.z = rna_tf32(v.z); v.w = rna_tf32(v.w);
    *reinterpret_cast<float4*>(dst + i) = v;
}

__global__ void reduce_big_kernel(const float* __restrict__ part,
                                  const float* __restrict__ rowp,
                                  float* __restrict__ agg) {
    const size_t i = (size_t)(blockIdx.x * blockDim.x + threadIdx.x) * 4;
    const int row = (int)(i >> 8);
    const float inv = 1.0f / (rowp[row] + rowp[N_NODES + row] +
                              rowp[2 * N_NODES + row] + rowp[3 * N_NODES + row] + 1.0f);
    const size_t MN = (size_t)N_NODES * F_DIM;
    float4 a = *reinterpret_cast<const float4*>(part + i);
    float4 b = *reinterpret_cast<const float4*>(part + MN + i);
    float4 c = *reinterpret_cast<const float4*>(part + 2 * MN + i);
    float4 d = *reinterpret_cast<const float4*>(part + 3 * MN + i);
    float4 o;
    o.x = rna_tf32((a.x + b.x + c.x + d.x) * inv);
    o.y = rna_tf32((a.y + b.y + c.y + d.y) * inv);
    o.z = rna_tf32((a.z + b.z + c.z + d.z) * inv);
    o.w = rna_tf32((a.w + b.w + c.w + d.w) * inv);
    *reinterpret_cast<float4*>(agg + i) = o;
}

__global__ void reduce_out_kernel(const float* __restrict__ part, float* __restrict__ out) {
    const size_t i = (size_t)(blockIdx.x * blockDim.x + threadIdx.x) * 4;
    const size_t MN = (size_t)N_NODES * F_DIM;
    float4 a = *reinterpret_cast<const float4*>(part + i);
    float4 b = *reinterpret_cast<const float4*>(part + MN + i);
    *reinterpret_cast<float4*>(out + i) =
        make_float4(a.x + b.x, a.y + b.y, a.z + b.z, a.w + b.w);
}

// ---------------------------------------------------------------------------
// NARROW kernel: tile 128x128x32, 256 threads (used for GEMM1 + concat GEMM3)
// ---------------------------------------------------------------------------
#define A_FLTS 4608              // 128*36
#define STAGE_FLTS_N (2 * A_FLTS)
#define NSTAGE 3
#define SMEM_N (NSTAGE * STAGE_FLTS_N * 4)   // 110592

template <bool CONCAT, bool ROUND_OUT>
__global__ __launch_bounds__(256, 2)
void tgemm(const float* __restrict__ A, const float* __restrict__ A2,
           const float* __restrict__ B, float* __restrict__ C,
           int K, int lda, int ldb, int ldc, size_t c_split_stride)
{
    extern __shared__ float sm[];
    const int tid  = threadIdx.x;
    const int lane = tid & 31;
    const int wid  = tid >> 5;
    const int wm   = wid & 1;
    const int wn   = wid >> 1;
    const int bm   = blockIdx.y * 128;
    const int bn   = blockIdx.x * 128;
    const int zz   = blockIdx.z;

    C += (size_t)zz * c_split_stride;
    const int koffB = zz * K;
    const float* Abase = (CONCAT && zz) ? A2 : A;
    const int koffA = CONCAT ? 0 : koffB;

    const uint32_t smem_base = (uint32_t)__cvta_generic_to_shared(sm);

    float acc[4][4][4];
    #pragma unroll
    for (int i = 0; i < 4; i++)
        #pragma unroll
        for (int j = 0; j < 4; j++)
            #pragma unroll
            for (int r = 0; r < 4; r++) acc[i][j][r] = 0.0f;

    uint32_t a_off, b_off;
    {
        const int ar = wm * 64 + (lane & 7) + ((lane >> 3) & 1) * 8;
        const int ak = ((lane >> 4) & 1) * 4;
        a_off = (uint32_t)(ar * 36 + ak) * 4u;
        const int br = wn * 32 + ((lane >> 4) & 1) * 8 + (lane & 7);
        const int bk = ((lane >> 3) & 1) * 4;
        b_off = (uint32_t)(br * 36 + bk) * 4u + A_FLTS * 4u;
    }

    const int a_r  = tid >> 3;
    const int a_kv = (tid & 7) * 4;

    auto fill = [&](int t) {
        const int k0 = t * 32;
        const int s  = t % NSTAGE;
        const uint32_t sA = smem_base + (uint32_t)(s * STAGE_FLTS_N) * 4u;
        const uint32_t sB = sA + A_FLTS * 4u;
        #pragma unroll
        for (int p = 0; p < 4; p++) {
            const int r = a_r + 32 * p;
            cp_async16(sA + (uint32_t)(r * 36 + a_kv) * 4u,
                       Abase + (size_t)(bm + r) * lda + koffA + k0 + a_kv);
        }
        #pragma unroll
        for (int p = 0; p < 4; p++) {
            const int n = a_r + 32 * p;
            cp_async16(sB + (uint32_t)(n * 36 + a_kv) * 4u,
                       B + (size_t)(bn + n) * ldb + koffB + k0 + a_kv);
        }
    };

    const int T = K >> 5;
    fill(0); cp_commit();
    fill(1); cp_commit();

    for (int t = 0; t < T; t++) {
        cp_wait<1>();
        __syncthreads();
        if (t + 2 < T) fill(t + 2);
        cp_commit();

        const int s = t % NSTAGE;
        const uint32_t stage_b = smem_base + (uint32_t)(s * STAGE_FLTS_N) * 4u;
        const uint32_t a_base = stage_b + a_off;
        const uint32_t b_base = stage_b + b_off;

        #pragma unroll
        for (int k8 = 0; k8 < 32; k8 += 8) {
            const uint32_t kb = (uint32_t)k8 * 4u;
            uint32_t af[4][4];
            #pragma unroll
            for (int mi = 0; mi < 4; mi++)
                ldsm_x4(af[mi][0], af[mi][1], af[mi][2], af[mi][3],
                        a_base + kb + (uint32_t)(mi * 16 * 36) * 4u);
            uint32_t bf[4][2];
            #pragma unroll
            for (int pi = 0; pi < 2; pi++)
                ldsm_x4(bf[2 * pi][0], bf[2 * pi][1], bf[2 * pi + 1][0], bf[2 * pi + 1][1],
                        b_base + kb + (uint32_t)(pi * 16 * 36) * 4u);
            #pragma unroll
            for (int mi = 0; mi < 4; mi++)
                #pragma unroll
                for (int ni = 0; ni < 4; ni++)
                    mma_tf32(acc[mi][ni], af[mi], bf[ni]);
        }
    }

    #pragma unroll
    for (int mi = 0; mi < 4; mi++) {
        const int r0 = bm + wm * 64 + mi * 16 + (lane >> 2);
        #pragma unroll
        for (int ni = 0; ni < 4; ni++) {
            const int c0 = bn + wn * 32 + ni * 8 + 2 * (lane & 3);
            float* p0 = C + (size_t)r0 * ldc + c0;
            float* p1 = C + (size_t)(r0 + 8) * ldc + c0;
            float2 v0 = make_float2(acc[mi][ni][0], acc[mi][ni][1]);
            float2 v1 = make_float2(acc[mi][ni][2], acc[mi][ni][3]);
            if (ROUND_OUT) {
                v0.x = rna_tf32(v0.x); v0.y = rna_tf32(v0.y);
                v1.x = rna_tf32(v1.x); v1.y = rna_tf32(v1.y);
            }
            *reinterpret_cast<float2*>(p0) = v0;
            *reinterpret_cast<float2*>(p1) = v1;
        }
    }
}

// ---------------------------------------------------------------------------
// WIDE kernel (big GEMM): tile 128x256x32, 512 threads, 16 warps (2x8, 64x32),
// 2-stage double buffer, fused partial rowsum, raw split-K partial output.
// grid (1, M/128, KSPLIT). adj read ONCE (N covers full F_DIM).
// ---------------------------------------------------------------------------
#define B_FLTS_W (256 * 36)                       // 9216
#define STAGE_FLTS_W (A_FLTS + B_FLTS_W)          // 13824
#define SMEM_W (2 * STAGE_FLTS_W * 4)             // 110592

__global__ __launch_bounds__(512, 2)
void tgemm_wide(const float* __restrict__ A, const float* __restrict__ B,
                float* __restrict__ C, float* __restrict__ rowp,
                int K, int lda, int ldb, int ldc, size_t c_split_stride)
{
    extern __shared__ float sm[];
    __shared__ float s_part[512];

    const int tid  = threadIdx.x;
    const int lane = tid & 31;
    const int wid  = tid >> 5;
    const int wm   = wid & 1;      // 2 warp-rows
    const int wn   = wid >> 1;     // 8 warp-cols
    const int bm   = blockIdx.y * 128;
    const int zz   = blockIdx.z;

    C += (size_t)zz * c_split_stride;
    const int koff = zz * K;

    const uint32_t smem_base = (uint32_t)__cvta_generic_to_shared(sm);

    float acc[4][4][4];
    #pragma unroll
    for (int i = 0; i < 4; i++)
        #pragma unroll
        for (int j = 0; j < 4; j++)
            #pragma unroll
            for (int r = 0; r < 4; r++) acc[i][j][r] = 0.0f;

    uint32_t a_off, b_off;
    {
        const int ar = wm * 64 + (lane & 7) + ((lane >> 3) & 1) * 8;
        const int ak = ((lane >> 4) & 1) * 4;
        a_off = (uint32_t)(ar * 36 + ak) * 4u;
        const int br = wn * 32 + ((lane >> 4) & 1) * 8 + (lane & 7);
        const int bk = ((lane >> 3) & 1) * 4;
        b_off = (uint32_t)(br * 36 + bk) * 4u + A_FLTS * 4u;
    }

    const int l_r  = tid >> 3;          // 0..63
    const int l_kv = (tid & 7) * 4;     // 0..28

    auto fill = [&](int t) {
        const int k0 = koff + t * 32;
        const int s  = t & 1;
        const uint32_t sA = smem_base + (uint32_t)(s * STAGE_FLTS_W) * 4u;
        const uint32_t sB = sA + A_FLTS * 4u;
        #pragma unroll
        for (int p = 0; p < 2; p++) {
            const int r = l_r + 64 * p;
            cp_async16(sA + (uint32_t)(r * 36 + l_kv) * 4u,
                       A + (size_t)(bm + r) * lda + k0 + l_kv);
        }
        #pragma unroll
        for (int p = 0; p < 4; p++) {
            const int n = l_r + 64 * p;
            cp_async16(sB + (uint32_t)(n * 36 + l_kv) * 4u,
                       B + (size_t)n * ldb + k0 + l_kv);
        }
        cp_commit();
    };

    float row_acc = 0.0f;
    const int T = K >> 5;

    fill(0);

    for (int t = 0; t < T; t++) {
        cp_wait<0>();
        __syncthreads();             // data ready + all warps done with prev slot
        if (t + 1 < T) fill(t + 1);  // overlaps compute below

        const int s = t & 1;
        const uint32_t stage_b = smem_base + (uint32_t)(s * STAGE_FLTS_W) * 4u;
        const uint32_t a_base = stage_b + a_off;
        const uint32_t b_base = stage_b + b_off;

        #pragma unroll
        for (int k8 = 0; k8 < 32; k8 += 8) {
            const uint32_t kb = (uint32_t)k8 * 4u;
            uint32_t af[4][4];
            #pragma unroll
            for (int mi = 0; mi < 4; mi++)
                ldsm_x4(af[mi][0], af[mi][1], af[mi][2], af[mi][3],
                        a_base + kb + (uint32_t)(mi * 16 * 36) * 4u);
            uint32_t bf[4][2];
            #pragma unroll
            for (int pi = 0; pi < 2; pi++)
                ldsm_x4(bf[2 * pi][0], bf[2 * pi][1], bf[2 * pi + 1][0], bf[2 * pi + 1][1],
                        b_base + kb + (uint32_t)(pi * 16 * 36) * 4u);
            #pragma unroll
            for (int mi = 0; mi < 4; mi++)
                #pragma unroll
                for (int ni = 0; ni < 4; ni++)
                    mma_tf32(acc[mi][ni], af[mi], bf[ni]);
        }

        // fused partial rowsum: 4 threads per A row, 8 floats each
        {
            const float* Ar = sm + s * STAGE_FLTS_W + (tid >> 2) * 36 + (tid & 3) * 8;
            const int rot = (tid >> 2) & 1;
            float st = 0.0f;
            #pragma unroll
            for (int i = 0; i < 2; i++) {
                const float4 v = *(const float4*)(Ar + (((i + rot) & 1) * 4));
                st += (v.x + v.y) + (v.z + v.w);
            }
            row_acc += st;
        }
        __syncthreads();             // all reads of slot s done before refill
    }

    s_part[tid] = row_acc;
    __syncthreads();
    if (tid < 128 && blockIdx.x == 0)
        rowp[(size_t)zz * N_NODES + bm + tid] =
            ((s_part[4 * tid] + s_part[4 * tid + 1]) +
             (s_part[4 * tid + 2] + s_part[4 * tid + 3]));

    #pragma unroll
    for (int mi = 0; mi < 4; mi++) {
        const int r0 = bm + wm * 64 + mi * 16 + (lane >> 2);
        #pragma unroll
        for (int ni = 0; ni < 4; ni++) {
            const int c0 = wn * 32 + ni * 8 + 2 * (lane & 3);
            float* p0 = C + (size_t)r0 * ldc + c0;
            float* p1 = C + (size_t)(r0 + 8) * ldc + c0;
            *reinterpret_cast<float2*>(p0) = make_float2(acc[mi][ni][0], acc[mi][ni][1]);
            *reinterpret_cast<float2*>(p1) = make_float2(acc[mi][ni][2], acc[mi][ni][3]);
        }
    }
}

// ---------------------------------------------------------------------------
extern "C" void kernel_launch(void* const* d_in, const int* in_sizes, int n_in,
                              void* d_out, int out_size)
{
    const float* features = (const float*)d_in[0];  // [8192, 256]
    const float* adj      = (const float*)d_in[1];  // [8192, 8192]
    const float* neigh_W  = (const float*)d_in[2];  // [256, 256]
    const float* lin_W    = (const float*)d_in[3];  // [256, 512]
    float* out = (float*)d_out;                     // [8192, 256]

    float *hT, *agg, *feat, *part, *rowp;
    cudaGetSymbolAddress((void**)&hT,   g_hT);
    cudaGetSymbolAddress((void**)&agg,  g_agg);
    cudaGetSymbolAddress((void**)&feat, g_feat);
    cudaGetSymbolAddress((void**)&part, g_part);
    cudaGetSymbolAddress((void**)&rowp, g_rowp);

    cudaFuncSetAttribute(tgemm<false, true >,
                         cudaFuncAttributeMaxDynamicSharedMemorySize, SMEM_N);
    cudaFuncSetAttribute(tgemm<true,  false>,
                         cudaFuncAttributeMaxDynamicSharedMemorySize, SMEM_N);
    cudaFuncSetAttribute(tgemm_wide,
                         cudaFuncAttributeMaxDynamicSharedMemorySize, SMEM_W);

    const size_t MN = (size_t)N_NODES * F_DIM;

    // 0) feat = round_tf32(features)
    round_copy_kernel<<<1024, 512>>>(features, feat);

    // 1) hT = rna(neigh_W @ feat^T)   M=256, N=8192, K=256
    tgemm<false, true><<<dim3(64, 2, 1), 256, SMEM_N>>>(
        neigh_W, nullptr, feat, hT, F_DIM, F_DIM, F_DIM, N_NODES, 0);

    // 2) split-K x4 partials of adj @ hT^T (+ partial rowsums)
    //    tile 128x256, grid (1, 64, 4) = 256 CTAs, adj read once
    tgemm_wide<<<dim3(1, 64, KSPLIT), 512, SMEM_W>>>(
        adj, hT, part, rowp, KCHUNK, N_NODES, N_NODES, F_DIM, MN);

    // 2b) agg = rna( (sum parts) / (sum rowsums + 1) )
    reduce_big_kernel<<<2048, 256>>>(part, rowp, agg);

    // 3) split concat GEMM: z=0: feat @ lin_W[:, :256]^T; z=1: agg @ lin_W[:, 256:]^T
    tgemm<true, false><<<dim3(2, 64, 2), 256, SMEM_N>>>(
        feat, agg, lin_W, part, F_DIM, F_DIM, 2 * F_DIM, F_DIM, MN);

    // 3b) out = part0 + part1
    reduce_out_kernel<<<2048, 256>>>(part, out);
}

// round 9
// speedup vs baseline: 3.2422x; 3.2422x over previous
#include <cuda_runtime.h>
#include <cstdint>

#define N_NODES 8192
#define F_DIM   256
#define KSPLIT  4
#define KCHUNK  (N_NODES / KSPLIT)   // 2048

// Scratch (no cudaMalloc allowed)
__device__ float g_hT[(size_t)F_DIM * N_NODES];            // rna(neigh_W @ feat^T) [256][8192]
__device__ float g_agg[(size_t)N_NODES * F_DIM];           // (adj@h)/deg, tf32-rounded
__device__ float g_feat[(size_t)N_NODES * F_DIM];          // tf32-rounded features
__device__ float g_part[(size_t)KSPLIT * N_NODES * F_DIM]; // split-K partials (32MB)
__device__ float g_rowp[(size_t)KSPLIT * N_NODES];         // partial rowsums

// ---------------------------------------------------------------------------
// helpers
// ---------------------------------------------------------------------------
__device__ __forceinline__ void cp_async16(uint32_t s, const void* g) {
    asm volatile("cp.async.cg.shared.global [%0], [%1], 16;\n" :: "r"(s), "l"(g));
}
__device__ __forceinline__ void cp_commit() { asm volatile("cp.async.commit_group;\n"); }
template <int N> __device__ __forceinline__ void cp_wait() {
    asm volatile("cp.async.wait_group %0;\n" :: "n"(N));
}
__device__ __forceinline__ float rna_tf32(float f) {
    uint32_t r;
    asm("cvt.rna.tf32.f32 %0, %1;\n" : "=r"(r) : "f"(f));
    return __uint_as_float(r);
}
__device__ __forceinline__ void mma_tf32(float* c, const uint32_t* a, const uint32_t* b) {
    asm volatile(
        "mma.sync.aligned.m16n8k8.row.col.f32.tf32.tf32.f32 "
        "{%0,%1,%2,%3}, {%4,%5,%6,%7}, {%8,%9}, {%0,%1,%2,%3};\n"
        : "+f"(c[0]), "+f"(c[1]), "+f"(c[2]), "+f"(c[3])
        : "r"(a[0]), "r"(a[1]), "r"(a[2]), "r"(a[3]), "r"(b[0]), "r"(b[1]));
}
__device__ __forceinline__ void ldsm_x4(uint32_t& r0, uint32_t& r1, uint32_t& r2,
                                        uint32_t& r3, uint32_t a) {
    asm volatile("ldmatrix.sync.aligned.m8n8.x4.shared.b16 {%0,%1,%2,%3}, [%4];\n"
                 : "=r"(r0), "=r"(r1), "=r"(r2), "=r"(r3) : "r"(a));
}

// ---------------------------------------------------------------------------
__global__ void round_copy_kernel(const float* __restrict__ src, float* __restrict__ dst) {
    const size_t i = (size_t)(blockIdx.x * blockDim.x + threadIdx.x) * 4;
    float4 v = *reinterpret_cast<const float4*>(src + i);
    v.x = rna_tf32(v.x); v.y = rna_tf32(v.y);
    v.z = rna_tf32(v.z); v.w = rna_tf32(v.w);
    *reinterpret_cast<float4*>(dst + i) = v;
}

__global__ void reduce_big_kernel(const float* __restrict__ part,
                                  const float* __restrict__ rowp,
                                  float* __restrict__ agg) {
    const size_t i = (size_t)(blockIdx.x * blockDim.x + threadIdx.x) * 4;
    const int row = (int)(i >> 8);
    const float inv = 1.0f / (rowp[row] + rowp[N_NODES + row] +
                              rowp[2 * N_NODES + row] + rowp[3 * N_NODES + row] + 1.0f);
    const size_t MN = (size_t)N_NODES * F_DIM;
    float4 a = *reinterpret_cast<const float4*>(part + i);
    float4 b = *reinterpret_cast<const float4*>(part + MN + i);
    float4 c = *reinterpret_cast<const float4*>(part + 2 * MN + i);
    float4 d = *reinterpret_cast<const float4*>(part + 3 * MN + i);
    float4 o;
    o.x = rna_tf32((a.x + b.x + c.x + d.x) * inv);
    o.y = rna_tf32((a.y + b.y + c.y + d.y) * inv);
    o.z = rna_tf32((a.z + b.z + c.z + d.z) * inv);
    o.w = rna_tf32((a.w + b.w + c.w + d.w) * inv);
    *reinterpret_cast<float4*>(agg + i) = o;
}

__global__ void reduce_out_kernel(const float* __restrict__ part, float* __restrict__ out) {
    const size_t i = (size_t)(blockIdx.x * blockDim.x + threadIdx.x) * 4;
    const size_t MN = (size_t)N_NODES * F_DIM;
    float4 a = *reinterpret_cast<const float4*>(part + i);
    float4 b = *reinterpret_cast<const float4*>(part + MN + i);
    *reinterpret_cast<float4*>(out + i) =
        make_float4(a.x + b.x, a.y + b.y, a.z + b.z, a.w + b.w);
}

// ---------------------------------------------------------------------------
// NARROW kernel: tile 128x128x32, 256 threads, 2 CTAs/SM (GEMM1 + concat GEMM3)
// ---------------------------------------------------------------------------
#define A_FLTS 4608              // 128*36
#define STAGE_FLTS_N (2 * A_FLTS)
#define NSTAGE 3
#define SMEM_N (NSTAGE * STAGE_FLTS_N * 4)   // 110592

template <bool CONCAT, bool ROUND_OUT>
__global__ __launch_bounds__(256, 2)
void tgemm(const float* __restrict__ A, const float* __restrict__ A2,
           const float* __restrict__ B, float* __restrict__ C,
           int K, int lda, int ldb, int ldc, size_t c_split_stride)
{
    extern __shared__ float sm[];
    const int tid  = threadIdx.x;
    const int lane = tid & 31;
    const int wid  = tid >> 5;
    const int wm   = wid & 1;
    const int wn   = wid >> 1;
    const int bm   = blockIdx.y * 128;
    const int bn   = blockIdx.x * 128;
    const int zz   = blockIdx.z;

    C += (size_t)zz * c_split_stride;
    const int koffB = zz * K;
    const float* Abase = (CONCAT && zz) ? A2 : A;
    const int koffA = CONCAT ? 0 : koffB;

    const uint32_t smem_base = (uint32_t)__cvta_generic_to_shared(sm);

    float acc[4][4][4];
    #pragma unroll
    for (int i = 0; i < 4; i++)
        #pragma unroll
        for (int j = 0; j < 4; j++)
            #pragma unroll
            for (int r = 0; r < 4; r++) acc[i][j][r] = 0.0f;

    uint32_t a_off, b_off;
    {
        const int ar = wm * 64 + (lane & 7) + ((lane >> 3) & 1) * 8;
        const int ak = ((lane >> 4) & 1) * 4;
        a_off = (uint32_t)(ar * 36 + ak) * 4u;
        const int br = wn * 32 + ((lane >> 4) & 1) * 8 + (lane & 7);
        const int bk = ((lane >> 3) & 1) * 4;
        b_off = (uint32_t)(br * 36 + bk) * 4u + A_FLTS * 4u;
    }

    const int a_r  = tid >> 3;
    const int a_kv = (tid & 7) * 4;

    auto fill = [&](int t) {
        const int k0 = t * 32;
        const int s  = t % NSTAGE;
        const uint32_t sA = smem_base + (uint32_t)(s * STAGE_FLTS_N) * 4u;
        const uint32_t sB = sA + A_FLTS * 4u;
        #pragma unroll
        for (int p = 0; p < 4; p++) {
            const int r = a_r + 32 * p;
            cp_async16(sA + (uint32_t)(r * 36 + a_kv) * 4u,
                       Abase + (size_t)(bm + r) * lda + koffA + k0 + a_kv);
        }
        #pragma unroll
        for (int p = 0; p < 4; p++) {
            const int n = a_r + 32 * p;
            cp_async16(sB + (uint32_t)(n * 36 + a_kv) * 4u,
                       B + (size_t)(bn + n) * ldb + koffB + k0 + a_kv);
        }
    };

    const int T = K >> 5;
    fill(0); cp_commit();
    fill(1); cp_commit();

    for (int t = 0; t < T; t++) {
        cp_wait<1>();
        __syncthreads();
        if (t + 2 < T) fill(t + 2);
        cp_commit();

        const int s = t % NSTAGE;
        const uint32_t stage_b = smem_base + (uint32_t)(s * STAGE_FLTS_N) * 4u;
        const uint32_t a_base = stage_b + a_off;
        const uint32_t b_base = stage_b + b_off;

        #pragma unroll
        for (int k8 = 0; k8 < 32; k8 += 8) {
            const uint32_t kb = (uint32_t)k8 * 4u;
            uint32_t af[4][4];
            #pragma unroll
            for (int mi = 0; mi < 4; mi++)
                ldsm_x4(af[mi][0], af[mi][1], af[mi][2], af[mi][3],
                        a_base + kb + (uint32_t)(mi * 16 * 36) * 4u);
            uint32_t bf[4][2];
            #pragma unroll
            for (int pi = 0; pi < 2; pi++)
                ldsm_x4(bf[2 * pi][0], bf[2 * pi][1], bf[2 * pi + 1][0], bf[2 * pi + 1][1],
                        b_base + kb + (uint32_t)(pi * 16 * 36) * 4u);
            #pragma unroll
            for (int mi = 0; mi < 4; mi++)
                #pragma unroll
                for (int ni = 0; ni < 4; ni++)
                    mma_tf32(acc[mi][ni], af[mi], bf[ni]);
        }
    }

    #pragma unroll
    for (int mi = 0; mi < 4; mi++) {
        const int r0 = bm + wm * 64 + mi * 16 + (lane >> 2);
        #pragma unroll
        for (int ni = 0; ni < 4; ni++) {
            const int c0 = bn + wn * 32 + ni * 8 + 2 * (lane & 3);
            float* p0 = C + (size_t)r0 * ldc + c0;
            float* p1 = C + (size_t)(r0 + 8) * ldc + c0;
            float2 v0 = make_float2(acc[mi][ni][0], acc[mi][ni][1]);
            float2 v1 = make_float2(acc[mi][ni][2], acc[mi][ni][3]);
            if (ROUND_OUT) {
                v0.x = rna_tf32(v0.x); v0.y = rna_tf32(v0.y);
                v1.x = rna_tf32(v1.x); v1.y = rna_tf32(v1.y);
            }
            *reinterpret_cast<float2*>(p0) = v0;
            *reinterpret_cast<float2*>(p1) = v1;
        }
    }
}

// ---------------------------------------------------------------------------
// WIDE kernel (big GEMM): tile 128x256x32, 512 threads, 16 warps (2x8, 64x32),
// __launch_bounds__(512, 1): full register budget, NO spill (R8's bug).
// 3-stage cp.async ring, fused partial rowsum, raw split-K partials.
// grid (1, 64, KSPLIT): adj read once from L2/DRAM.
// ---------------------------------------------------------------------------
#define B_FLTS_W (256 * 36)                       // 9216
#define STAGE_FLTS_W (A_FLTS + B_FLTS_W)          // 13824
#define SMEM_W (NSTAGE * STAGE_FLTS_W * 4)        // 165888

__global__ __launch_bounds__(512, 1)
void tgemm_wide(const float* __restrict__ A, const float* __restrict__ B,
                float* __restrict__ C, float* __restrict__ rowp,
                int K, int lda, int ldb, int ldc, size_t c_split_stride)
{
    extern __shared__ float sm[];
    __shared__ float s_part[512];

    const int tid  = threadIdx.x;
    const int lane = tid & 31;
    const int wid  = tid >> 5;
    const int wm   = wid & 1;      // 2 warp-rows
    const int wn   = wid >> 1;     // 8 warp-cols
    const int bm   = blockIdx.y * 128;
    const int zz   = blockIdx.z;

    C += (size_t)zz * c_split_stride;
    const int koff = zz * K;

    const uint32_t smem_base = (uint32_t)__cvta_generic_to_shared(sm);

    float acc[4][4][4];
    #pragma unroll
    for (int i = 0; i < 4; i++)
        #pragma unroll
        for (int j = 0; j < 4; j++)
            #pragma unroll
            for (int r = 0; r < 4; r++) acc[i][j][r] = 0.0f;

    uint32_t a_off, b_off;
    {
        const int ar = wm * 64 + (lane & 7) + ((lane >> 3) & 1) * 8;
        const int ak = ((lane >> 4) & 1) * 4;
        a_off = (uint32_t)(ar * 36 + ak) * 4u;
        const int br = wn * 32 + ((lane >> 4) & 1) * 8 + (lane & 7);
        const int bk = ((lane >> 3) & 1) * 4;
        b_off = (uint32_t)(br * 36 + bk) * 4u + A_FLTS * 4u;
    }

    const int l_r  = tid >> 3;          // 0..63
    const int l_kv = (tid & 7) * 4;     // 0..28

    auto fill = [&](int t) {
        const int k0 = koff + t * 32;
        const int s  = t % NSTAGE;
        const uint32_t sA = smem_base + (uint32_t)(s * STAGE_FLTS_W) * 4u;
        const uint32_t sB = sA + A_FLTS * 4u;
        #pragma unroll
        for (int p = 0; p < 2; p++) {
            const int r = l_r + 64 * p;
            cp_async16(sA + (uint32_t)(r * 36 + l_kv) * 4u,
                       A + (size_t)(bm + r) * lda + k0 + l_kv);
        }
        #pragma unroll
        for (int p = 0; p < 4; p++) {
            const int n = l_r + 64 * p;
            cp_async16(sB + (uint32_t)(n * 36 + l_kv) * 4u,
                       B + (size_t)n * ldb + k0 + l_kv);
        }
    };

    float row_acc = 0.0f;
    const int T = K >> 5;

    fill(0); cp_commit();
    fill(1); cp_commit();

    for (int t = 0; t < T; t++) {
        cp_wait<1>();
        __syncthreads();
        if (t + 2 < T) fill(t + 2);
        cp_commit();

        const int s = t % NSTAGE;
        const uint32_t stage_b = smem_base + (uint32_t)(s * STAGE_FLTS_W) * 4u;
        const uint32_t a_base = stage_b + a_off;
        const uint32_t b_base = stage_b + b_off;

        #pragma unroll
        for (int k8 = 0; k8 < 32; k8 += 8) {
            const uint32_t kb = (uint32_t)k8 * 4u;
            uint32_t af[4][4];
            #pragma unroll
            for (int mi = 0; mi < 4; mi++)
                ldsm_x4(af[mi][0], af[mi][1], af[mi][2], af[mi][3],
                        a_base + kb + (uint32_t)(mi * 16 * 36) * 4u);
            uint32_t bf[4][2];
            #pragma unroll
            for (int pi = 0; pi < 2; pi++)
                ldsm_x4(bf[2 * pi][0], bf[2 * pi][1], bf[2 * pi + 1][0], bf[2 * pi + 1][1],
                        b_base + kb + (uint32_t)(pi * 16 * 36) * 4u);
            #pragma unroll
            for (int mi = 0; mi < 4; mi++)
                #pragma unroll
                for (int ni = 0; ni < 4; ni++)
                    mma_tf32(acc[mi][ni], af[mi], bf[ni]);
        }

        // fused partial rowsum: 4 threads per A row, 8 floats each
        {
            const float* Ar = sm + s * STAGE_FLTS_W + (tid >> 2) * 36 + (tid & 3) * 8;
            const int rot = (tid >> 2) & 1;
            float st = 0.0f;
            #pragma unroll
            for (int i = 0; i < 2; i++) {
                const float4 v = *(const float4*)(Ar + (((i + rot) & 1) * 4));
                st += (v.x + v.y) + (v.z + v.w);
            }
            row_acc += st;
        }
    }

    __syncthreads();
    s_part[tid] = row_acc;
    __syncthreads();
    if (tid < 128)
        rowp[(size_t)zz * N_NODES + bm + tid] =
            ((s_part[4 * tid] + s_part[4 * tid + 1]) +
             (s_part[4 * tid + 2] + s_part[4 * tid + 3]));

    #pragma unroll
    for (int mi = 0; mi < 4; mi++) {
        const int r0 = bm + wm * 64 + mi * 16 + (lane >> 2);
        #pragma unroll
        for (int ni = 0; ni < 4; ni++) {
            const int c0 = wn * 32 + ni * 8 + 2 * (lane & 3);
            float* p0 = C + (size_t)r0 * ldc + c0;
            float* p1 = C + (size_t)(r0 + 8) * ldc + c0;
            *reinterpret_cast<float2*>(p0) = make_float2(acc[mi][ni][0], acc[mi][ni][1]);
            *reinterpret_cast<float2*>(p1) = make_float2(acc[mi][ni][2], acc[mi][ni][3]);
        }
    }
}

// ---------------------------------------------------------------------------
extern "C" void kernel_launch(void* const* d_in, const int* in_sizes, int n_in,
                              void* d_out, int out_size)
{
    const float* features = (const float*)d_in[0];  // [8192, 256]
    const float* adj      = (const float*)d_in[1];  // [8192, 8192]
    const float* neigh_W  = (const float*)d_in[2];  // [256, 256]
    const float* lin_W    = (const float*)d_in[3];  // [256, 512]
    float* out = (float*)d_out;                     // [8192, 256]

    float *hT, *agg, *feat, *part, *rowp;
    cudaGetSymbolAddress((void**)&hT,   g_hT);
    cudaGetSymbolAddress((void**)&agg,  g_agg);
    cudaGetSymbolAddress((void**)&feat, g_feat);
    cudaGetSymbolAddress((void**)&part, g_part);
    cudaGetSymbolAddress((void**)&rowp, g_rowp);

    cudaFuncSetAttribute(tgemm<false, true >,
                         cudaFuncAttributeMaxDynamicSharedMemorySize, SMEM_N);
    cudaFuncSetAttribute(tgemm<true,  false>,
                         cudaFuncAttributeMaxDynamicSharedMemorySize, SMEM_N);
    cudaFuncSetAttribute(tgemm_wide,
                         cudaFuncAttributeMaxDynamicSharedMemorySize, SMEM_W);

    const size_t MN = (size_t)N_NODES * F_DIM;

    // 0) feat = round_tf32(features)
    round_copy_kernel<<<1024, 512>>>(features, feat);

    // 1) hT = rna(neigh_W @ feat^T)   M=256, N=8192, K=256
    tgemm<false, true><<<dim3(64, 2, 1), 256, SMEM_N>>>(
        neigh_W, nullptr, feat, hT, F_DIM, F_DIM, F_DIM, N_NODES, 0);

    // 2) split-K x4 partials of adj @ hT^T (+ partial rowsums)
    //    tile 128x256, grid (1, 64, 4) = 256 CTAs, adj read once
    tgemm_wide<<<dim3(1, 64, KSPLIT), 512, SMEM_W>>>(
        adj, hT, part, rowp, KCHUNK, N_NODES, N_NODES, F_DIM, MN);

    // 2b) agg = rna( (sum parts) / (sum rowsums + 1) )
    reduce_big_kernel<<<2048, 256>>>(part, rowp, agg);

    // 3) split concat GEMM: z=0: feat @ lin_W[:, :256]^T; z=1: agg @ lin_W[:, 256:]^T
    tgemm<true, false><<<dim3(2, 64, 2), 256, SMEM_N>>>(
        feat, agg, lin_W, part, F_DIM, F_DIM, 2 * F_DIM, F_DIM, MN);

    // 3b) out = part0 + part1
    reduce_out_kernel<<<2048, 256>>>(part, out);
}

// round 10
// speedup vs baseline: 3.5924x; 1.1080x over previous
#include <cuda_runtime.h>
#include <cstdint>

#define N_NODES 8192
#define F_DIM   256
#define MN      ((size_t)N_NODES * F_DIM)

// Persistent-G2 work assignment: 2048 units = 128 tiles x 16 k-chunks(512).
// 296 CTAs: first 272 own 7 units, last 24 own 6. (272*7 + 24*6 = 2048)
#define NCTA_P   296
#define UNITS    2048
#define BIGQ     1904     // 272*7

// Scratch (no cudaMalloc allowed)
__device__ float g_hT[(size_t)F_DIM * N_NODES];   // rna(neigh_W @ feat^T) [256][8192]
__device__ float g_agg[MN];                        // (adj@h)/deg, tf32-rounded
__device__ float g_feat[MN];                       // tf32-rounded features
__device__ float g_part[4 * MN];                   // per-slot partials (32MB)
__device__ float g_rowp[4 * N_NODES];              // per-slot partial rowsums

// ---------------------------------------------------------------------------
// helpers
// ---------------------------------------------------------------------------
__device__ __forceinline__ void cp_async16(uint32_t s, const void* g) {
    asm volatile("cp.async.cg.shared.global [%0], [%1], 16;\n" :: "r"(s), "l"(g));
}
__device__ __forceinline__ void cp_commit() { asm volatile("cp.async.commit_group;\n"); }
template <int N> __device__ __forceinline__ void cp_wait() {
    asm volatile("cp.async.wait_group %0;\n" :: "n"(N));
}
__device__ __forceinline__ float rna_tf32(float f) {
    uint32_t r;
    asm("cvt.rna.tf32.f32 %0, %1;\n" : "=r"(r) : "f"(f));
    return __uint_as_float(r);
}
__device__ __forceinline__ void mma_tf32(float* c, const uint32_t* a, const uint32_t* b) {
    asm volatile(
        "mma.sync.aligned.m16n8k8.row.col.f32.tf32.tf32.f32 "
        "{%0,%1,%2,%3}, {%4,%5,%6,%7}, {%8,%9}, {%0,%1,%2,%3};\n"
        : "+f"(c[0]), "+f"(c[1]), "+f"(c[2]), "+f"(c[3])
        : "r"(a[0]), "r"(a[1]), "r"(a[2]), "r"(a[3]), "r"(b[0]), "r"(b[1]));
}
__device__ __forceinline__ void ldsm_x4(uint32_t& r0, uint32_t& r1, uint32_t& r2,
                                        uint32_t& r3, uint32_t a) {
    asm volatile("ldmatrix.sync.aligned.m8n8.x4.shared.b16 {%0,%1,%2,%3}, [%4];\n"
                 : "=r"(r0), "=r"(r1), "=r"(r2), "=r"(r3) : "r"(a));
}
__device__ __forceinline__ int unit_owner(int u) {
    return (u < BIGQ) ? (u / 7) : (272 + (u - BIGQ) / 6);
}

// ---------------------------------------------------------------------------
__global__ void round_copy_kernel(const float* __restrict__ src, float* __restrict__ dst) {
    const size_t i = (size_t)(blockIdx.x * blockDim.x + threadIdx.x) * 4;
    float4 v = *reinterpret_cast<const float4*>(src + i);
    v.x = rna_tf32(v.x); v.y = rna_tf32(v.y);
    v.z = rna_tf32(v.z); v.w = rna_tf32(v.w);
    *reinterpret_cast<float4*>(dst + i) = v;
}

// zero slot 3 of part + rowp (slots 0-2 always written by the persistent GEMM)
__global__ void zero_slot3_kernel(float* __restrict__ part, float* __restrict__ rowp) {
    const size_t g = (size_t)blockIdx.x * blockDim.x + threadIdx.x;   // 0..524287
    *reinterpret_cast<float4*>(part + 3 * MN + g * 4) = make_float4(0, 0, 0, 0);
    if (g < N_NODES / 4)
        *reinterpret_cast<float4*>(rowp + 3 * N_NODES + g * 4) = make_float4(0, 0, 0, 0);
}

__global__ void reduce_big_kernel(const float* __restrict__ part,
                                  const float* __restrict__ rowp,
                                  float* __restrict__ agg) {
    const size_t i = (size_t)(blockIdx.x * blockDim.x + threadIdx.x) * 4;
    const int row = (int)(i >> 8);
    const float inv = 1.0f / (rowp[row] + rowp[N_NODES + row] +
                              rowp[2 * N_NODES + row] + rowp[3 * N_NODES + row] + 1.0f);
    float4 a = *reinterpret_cast<const float4*>(part + i);
    float4 b = *reinterpret_cast<const float4*>(part + MN + i);
    float4 c = *reinterpret_cast<const float4*>(part + 2 * MN + i);
    float4 d = *reinterpret_cast<const float4*>(part + 3 * MN + i);
    float4 o;
    o.x = rna_tf32((a.x + b.x + c.x + d.x) * inv);
    o.y = rna_tf32((a.y + b.y + c.y + d.y) * inv);
    o.z = rna_tf32((a.z + b.z + c.z + d.z) * inv);
    o.w = rna_tf32((a.w + b.w + c.w + d.w) * inv);
    *reinterpret_cast<float4*>(agg + i) = o;
}

// ---------------------------------------------------------------------------
// NARROW kernel: tile 128x128x32, 256 threads, 2 CTAs/SM (GEMM1 + concat GEMM3)
//   CONCAT: A k in [0,256) from A, [256,512) from A2 (per-stage k0 switch)
// ---------------------------------------------------------------------------
#define A_FLTS 4608              // 128*36
#define STAGE_FLTS_N (2 * A_FLTS)
#define NSTAGE 3
#define SMEM_N (NSTAGE * STAGE_FLTS_N * 4)   // 110592

template <bool CONCAT, bool ROUND_OUT>
__global__ __launch_bounds__(256, 2)
void tgemm(const float* __restrict__ A, const float* __restrict__ A2,
           const float* __restrict__ B, float* __restrict__ C,
           int K, int lda, int ldb, int ldc)
{
    extern __shared__ float sm[];
    const int tid  = threadIdx.x;
    const int lane = tid & 31;
    const int wid  = tid >> 5;
    const int wm   = wid & 1;
    const int wn   = wid >> 1;
    const int bm   = blockIdx.y * 128;
    const int bn   = blockIdx.x * 128;

    const uint32_t smem_base = (uint32_t)__cvta_generic_to_shared(sm);

    float acc[4][4][4];
    #pragma unroll
    for (int i = 0; i < 4; i++)
        #pragma unroll
        for (int j = 0; j < 4; j++)
            #pragma unroll
            for (int r = 0; r < 4; r++) acc[i][j][r] = 0.0f;

    uint32_t a_off, b_off;
    {
        const int ar = wm * 64 + (lane & 7) + ((lane >> 3) & 1) * 8;
        const int ak = ((lane >> 4) & 1) * 4;
        a_off = (uint32_t)(ar * 36 + ak) * 4u;
        const int br = wn * 32 + ((lane >> 4) & 1) * 8 + (lane & 7);
        const int bk = ((lane >> 3) & 1) * 4;
        b_off = (uint32_t)(br * 36 + bk) * 4u + A_FLTS * 4u;
    }

    const int a_r  = tid >> 3;
    const int a_kv = (tid & 7) * 4;

    auto fill = [&](int t) {
        const int k0 = t * 32;
        const int s  = t % NSTAGE;
        const uint32_t sA = smem_base + (uint32_t)(s * STAGE_FLTS_N) * 4u;
        const uint32_t sB = sA + A_FLTS * 4u;
        const float* Asrc = A;
        int ka = k0;
        if (CONCAT && k0 >= F_DIM) { Asrc = A2; ka = k0 - F_DIM; }
        #pragma unroll
        for (int p = 0; p < 4; p++) {
            const int r = a_r + 32 * p;
            cp_async16(sA + (uint32_t)(r * 36 + a_kv) * 4u,
                       Asrc + (size_t)(bm + r) * lda + ka + a_kv);
        }
        #pragma unroll
        for (int p = 0; p < 4; p++) {
            const int n = a_r + 32 * p;
            cp_async16(sB + (uint32_t)(n * 36 + a_kv) * 4u,
                       B + (size_t)(bn + n) * ldb + k0 + a_kv);
        }
    };

    const int T = K >> 5;
    fill(0); cp_commit();
    fill(1); cp_commit();

    for (int t = 0; t < T; t++) {
        cp_wait<1>();
        __syncthreads();
        if (t + 2 < T) fill(t + 2);
        cp_commit();

        const int s = t % NSTAGE;
        const uint32_t stage_b = smem_base + (uint32_t)(s * STAGE_FLTS_N) * 4u;
        const uint32_t a_base = stage_b + a_off;
        const uint32_t b_base = stage_b + b_off;

        #pragma unroll
        for (int k8 = 0; k8 < 32; k8 += 8) {
            const uint32_t kb = (uint32_t)k8 * 4u;
            uint32_t af[4][4];
            #pragma unroll
            for (int mi = 0; mi < 4; mi++)
                ldsm_x4(af[mi][0], af[mi][1], af[mi][2], af[mi][3],
                        a_base + kb + (uint32_t)(mi * 16 * 36) * 4u);
            uint32_t bf[4][2];
            #pragma unroll
            for (int pi = 0; pi < 2; pi++)
                ldsm_x4(bf[2 * pi][0], bf[2 * pi][1], bf[2 * pi + 1][0], bf[2 * pi + 1][1],
                        b_base + kb + (uint32_t)(pi * 16 * 36) * 4u);
            #pragma unroll
            for (int mi = 0; mi < 4; mi++)
                #pragma unroll
                for (int ni = 0; ni < 4; ni++)
                    mma_tf32(acc[mi][ni], af[mi], bf[ni]);
        }
    }

    #pragma unroll
    for (int mi = 0; mi < 4; mi++) {
        const int r0 = bm + wm * 64 + mi * 16 + (lane >> 2);
        #pragma unroll
        for (int ni = 0; ni < 4; ni++) {
            const int c0 = bn + wn * 32 + ni * 8 + 2 * (lane & 3);
            float* p0 = C + (size_t)r0 * ldc + c0;
            float* p1 = C + (size_t)(r0 + 8) * ldc + c0;
            float2 v0 = make_float2(acc[mi][ni][0], acc[mi][ni][1]);
            float2 v1 = make_float2(acc[mi][ni][2], acc[mi][ni][3]);
            if (ROUND_OUT) {
                v0.x = rna_tf32(v0.x); v0.y = rna_tf32(v0.y);
                v1.x = rna_tf32(v1.x); v1.y = rna_tf32(v1.y);
            }
            *reinterpret_cast<float2*>(p0) = v0;
            *reinterpret_cast<float2*>(p1) = v1;
        }
    }
}

// ---------------------------------------------------------------------------
// PERSISTENT big GEMM: 296 CTAs, statically balanced over 2048 (tile,k-chunk)
// units. Each run = contiguous k-chunks within one 128x128 output tile; flush
// raw partials (+ partial rowsum for bn==0 tiles) into slot = run ordinal.
// ---------------------------------------------------------------------------
__global__ __launch_bounds__(256, 2)
void tgemm_persist(const float* __restrict__ A, const float* __restrict__ B,
                   float* __restrict__ part, float* __restrict__ rowp)
{
    extern __shared__ float sm[];
    __shared__ float s_red[256];

    const int cta  = blockIdx.x;                      // 0..295
    int u          = (cta < 272) ? 7 * cta : BIGQ + 6 * (cta - 272);
    const int uend = u + ((cta < 272) ? 7 : 6);

    const int tid  = threadIdx.x;
    const int lane = tid & 31;
    const int wid  = tid >> 5;
    const int wm   = wid & 1;
    const int wn   = wid >> 1;

    const uint32_t smem_base = (uint32_t)__cvta_generic_to_shared(sm);

    uint32_t a_off, b_off;
    {
        const int ar = wm * 64 + (lane & 7) + ((lane >> 3) & 1) * 8;
        const int ak = ((lane >> 4) & 1) * 4;
        a_off = (uint32_t)(ar * 36 + ak) * 4u;
        const int br = wn * 32 + ((lane >> 4) & 1) * 8 + (lane & 7);
        const int bk = ((lane >> 3) & 1) * 4;
        b_off = (uint32_t)(br * 36 + bk) * 4u + A_FLTS * 4u;
    }
    const int a_r  = tid >> 3;
    const int a_kv = (tid & 7) * 4;

    while (u < uend) {
        const int tile   = u >> 4;
        const int kc0    = u & 15;
        const int runlen = min(uend - u, 16 - kc0);
        const int slot   = cta - unit_owner(tile << 4);   // 0..3
        const int bm     = (tile & 63) * 128;
        const int bn     = (tile >> 6) * 128;
        const int kbeg   = kc0 * 512;
        const int T      = runlen * 16;                   // stages of K=32

        float acc[4][4][4];
        #pragma unroll
        for (int i = 0; i < 4; i++)
            #pragma unroll
            for (int j = 0; j < 4; j++)
                #pragma unroll
                for (int r = 0; r < 4; r++) acc[i][j][r] = 0.0f;
        float row_acc = 0.0f;

        auto fill = [&](int t) {
            const int k0 = kbeg + t * 32;
            const int s  = t % NSTAGE;
            const uint32_t sA = smem_base + (uint32_t)(s * STAGE_FLTS_N) * 4u;
            const uint32_t sB = sA + A_FLTS * 4u;
            #pragma unroll
            for (int p = 0; p < 4; p++) {
                const int r = a_r + 32 * p;
                cp_async16(sA + (uint32_t)(r * 36 + a_kv) * 4u,
                           A + (size_t)(bm + r) * N_NODES + k0 + a_kv);
            }
            #pragma unroll
            for (int p = 0; p < 4; p++) {
                const int n = a_r + 32 * p;
                cp_async16(sB + (uint32_t)(n * 36 + a_kv) * 4u,
                           B + (size_t)(bn + n) * N_NODES + k0 + a_kv);
            }
        };

        fill(0); cp_commit();
        fill(1); cp_commit();

        for (int t = 0; t < T; t++) {
            cp_wait<1>();
            __syncthreads();
            if (t + 2 < T) fill(t + 2);
            cp_commit();

            const int s = t % NSTAGE;
            const uint32_t stage_b = smem_base + (uint32_t)(s * STAGE_FLTS_N) * 4u;
            const uint32_t a_base = stage_b + a_off;
            const uint32_t b_base = stage_b + b_off;

            #pragma unroll
            for (int k8 = 0; k8 < 32; k8 += 8) {
                const uint32_t kb = (uint32_t)k8 * 4u;
                uint32_t af[4][4];
                #pragma unroll
                for (int mi = 0; mi < 4; mi++)
                    ldsm_x4(af[mi][0], af[mi][1], af[mi][2], af[mi][3],
                            a_base + kb + (uint32_t)(mi * 16 * 36) * 4u);
                uint32_t bf[4][2];
                #pragma unroll
                for (int pi = 0; pi < 2; pi++)
                    ldsm_x4(bf[2 * pi][0], bf[2 * pi][1],
                            bf[2 * pi + 1][0], bf[2 * pi + 1][1],
                            b_base + kb + (uint32_t)(pi * 16 * 36) * 4u);
                #pragma unroll
                for (int mi = 0; mi < 4; mi++)
                    #pragma unroll
                    for (int ni = 0; ni < 4; ni++)
                        mma_tf32(acc[mi][ni], af[mi], bf[ni]);
            }

            // fused partial rowsum over adj tile (2 threads per row, 16 vals)
            {
                const float* Ar = sm + s * STAGE_FLTS_N + (tid >> 1) * 36 + (tid & 1) * 16;
                const int rot = (tid >> 1) & 3;
                float st = 0.0f;
                #pragma unroll
                for (int i = 0; i < 4; i++) {
                    const float4 v = *(const float4*)(Ar + (((i + rot) & 3) * 4));
                    st += (v.x + v.y) + (v.z + v.w);
                }
                row_acc += st;
            }
        }

        __syncthreads();    // all warps done reading the ring before next run

        if (bn == 0) {
            s_red[tid] = row_acc;
            __syncthreads();
            if (tid < 128)
                rowp[slot * N_NODES + bm + tid] =
                    s_red[2 * tid] + s_red[2 * tid + 1];
            __syncthreads();
        }

        float* C = part + (size_t)slot * MN;
        #pragma unroll
        for (int mi = 0; mi < 4; mi++) {
            const int r0 = bm + wm * 64 + mi * 16 + (lane >> 2);
            #pragma unroll
            for (int ni = 0; ni < 4; ni++) {
                const int c0 = bn + wn * 32 + ni * 8 + 2 * (lane & 3);
                *reinterpret_cast<float2*>(C + (size_t)r0 * F_DIM + c0) =
                    make_float2(acc[mi][ni][0], acc[mi][ni][1]);
                *reinterpret_cast<float2*>(C + (size_t)(r0 + 8) * F_DIM + c0) =
                    make_float2(acc[mi][ni][2], acc[mi][ni][3]);
            }
        }

        u += runlen;
    }
}

// ---------------------------------------------------------------------------
extern "C" void kernel_launch(void* const* d_in, const int* in_sizes, int n_in,
                              void* d_out, int out_size)
{
    const float* features = (const float*)d_in[0];  // [8192, 256]
    const float* adj      = (const float*)d_in[1];  // [8192, 8192]
    const float* neigh_W  = (const float*)d_in[2];  // [256, 256]
    const float* lin_W    = (const float*)d_in[3];  // [256, 512]
    float* out = (float*)d_out;                     // [8192, 256]

    float *hT, *agg, *feat, *part, *rowp;
    cudaGetSymbolAddress((void**)&hT,   g_hT);
    cudaGetSymbolAddress((void**)&agg,  g_agg);
    cudaGetSymbolAddress((void**)&feat, g_feat);
    cudaGetSymbolAddress((void**)&part, g_part);
    cudaGetSymbolAddress((void**)&rowp, g_rowp);

    cudaFuncSetAttribute(tgemm<false, true >,
                         cudaFuncAttributeMaxDynamicSharedMemorySize, SMEM_N);
    cudaFuncSetAttribute(tgemm<true,  false>,
                         cudaFuncAttributeMaxDynamicSharedMemorySize, SMEM_N);
    cudaFuncSetAttribute(tgemm_persist,
                         cudaFuncAttributeMaxDynamicSharedMemorySize, SMEM_N);

    // 1) feat = round_tf32(features)
    round_copy_kernel<<<1024, 512>>>(features, feat);

    // 2) hT = rna(neigh_W @ feat^T)   M=256, N=8192, K=256
    tgemm<false, true><<<dim3(64, 2), 256, SMEM_N>>>(
        neigh_W, nullptr, feat, hT, F_DIM, F_DIM, F_DIM, N_NODES);

    // 3) zero slot 3 (only conditionally-written slot)  [puts G2 at launch #4]
    zero_slot3_kernel<<<2048, 256>>>(part, rowp);

    // 4) persistent balanced adj @ hT^T partials (+ rowsums), 296 CTAs
    tgemm_persist<<<NCTA_P, 256, SMEM_N>>>(adj, hT, part, rowp);

    // 5) agg = rna( (sum of 4 slots) / (sum rowsums + 1) )
    reduce_big_kernel<<<2048, 256>>>(part, rowp, agg);

    // 6) out = [feat | agg] @ lin_W^T   (single-pass concat, K=512)
    tgemm<true, false><<<dim3(2, 64), 256, SMEM_N>>>(
        feat, agg, lin_W, out, 2 * F_DIM, F_DIM, 2 * F_DIM, F_DIM);
}